// round 1
// baseline (speedup 1.0000x reference)
#include <cuda_runtime.h>
#include <math.h>

// Problem constants (fixed by reference setup)
#define DIMC   768
#define NHEAD  12
#define HD     64
#define BATCH  4
#define SEQN   8192
#define MROWS  (BATCH * SEQN)   // 32768
#define C3     (3 * DIMC)       // 2304
#define NSPLIT 8
#define ROWS_PER_SPLIT (SEQN / NSPLIT)  // 1024
#define NBH    (BATCH * NHEAD)  // 48

// ---------------- Device scratch (no cudaMalloc allowed) ----------------
__device__ float g_Y[(size_t)MROWS * C3];                 // qkv activations  (~302 MB)
__device__ float g_Gp[(size_t)NBH * NSPLIT * HD * HD];    // Gram partials    (~6.3 MB)
__device__ float g_Sqp[(size_t)BATCH * NSPLIT * 2 * DIMC];// col sumsq partials
__device__ float g_A[(size_t)NBH * HD * HD];              // softmaxed attention
__device__ float g_Weff[(size_t)BATCH * DIMC * DIMC];     // per-batch folded proj weight

// =========================================================================
// K1 / K5: 128x128x8 SIMT fp32 GEMM with bias.
// MODE 0: Y = X @ Wqkv + bqkv          (A=Aext[M,768], B=Bext[768,2304], C=g_Y)
// MODE 1: Z = Yv @ Weff[b] + bproj     (A=g_Y+1536 ld 2304, B=g_Weff per batch, C=Cext)
// =========================================================================
template<int MODE>
__global__ __launch_bounds__(256)
void sgemm_bias(const float* __restrict__ Aext,
                const float* __restrict__ Bext,
                const float* __restrict__ bias,
                float* __restrict__ Cext)
{
    constexpr int BM = 128, BN = 128, BK = 8;
    constexpr int K = DIMC;

    __shared__ __align__(16) float As[BK][BM];
    __shared__ __align__(16) float Bs[BK][BN];

    const int t  = threadIdx.x;
    const int m0 = blockIdx.y * BM;
    const int n0 = blockIdx.x * BN;

    const float* A; const float* Bm; float* Cm;
    int lda, ldb, ldc;
    if (MODE == 0) {
        A = Aext;            lda = DIMC;
        Bm = Bext;           ldb = C3;
        Cm = g_Y;            ldc = C3;
    } else {
        A = g_Y + 2 * DIMC;  lda = C3;   // V columns of Y
        Bm = g_Weff + (size_t)(m0 / SEQN) * DIMC * DIMC; ldb = DIMC;
        Cm = Cext;           ldc = DIMC;
    }

    const float* Aptr = A + (size_t)m0 * lda;
    const float* Bptr = Bm + n0;

    // load assignments
    const int ar = t >> 1;            // 0..127 (A tile row)
    const int ak = (t & 1) * 4;       // 0 or 4 (A tile k quad)
    const int br = t >> 5;            // 0..7   (B tile k row)
    const int bc = (t & 31) * 4;      // 0..124 (B tile col quad)

    const int tx = t & 15;            // 0..15  -> 8 cols
    const int ty = t >> 4;            // 0..15  -> 8 rows

    float c[8][8] = {};

    for (int k0 = 0; k0 < K; k0 += BK) {
        float4 av = *(const float4*)(Aptr + (size_t)ar * lda + k0 + ak);
        As[ak + 0][ar] = av.x;
        As[ak + 1][ar] = av.y;
        As[ak + 2][ar] = av.z;
        As[ak + 3][ar] = av.w;
        *(float4*)&Bs[br][bc] =
            *(const float4*)(Bptr + (size_t)(k0 + br) * ldb + bc);
        __syncthreads();

#pragma unroll
        for (int kk = 0; kk < BK; kk++) {
            float a[8], b[8];
            *(float4*)(a)     = *(const float4*)&As[kk][ty * 8];
            *(float4*)(a + 4) = *(const float4*)&As[kk][ty * 8 + 4];
            *(float4*)(b)     = *(const float4*)&Bs[kk][tx * 8];
            *(float4*)(b + 4) = *(const float4*)&Bs[kk][tx * 8 + 4];
#pragma unroll
            for (int i = 0; i < 8; i++)
#pragma unroll
                for (int j = 0; j < 8; j++)
                    c[i][j] += a[i] * b[j];
        }
        __syncthreads();
    }

    // epilogue: + bias
    float bcol[8];
#pragma unroll
    for (int j = 0; j < 8; j++) bcol[j] = bias[n0 + tx * 8 + j];

#pragma unroll
    for (int i = 0; i < 8; i++) {
        const int row = m0 + ty * 8 + i;
        float* cp = Cm + (size_t)row * ldc + n0 + tx * 8;
        float4 v0, v1;
        v0.x = c[i][0] + bcol[0]; v0.y = c[i][1] + bcol[1];
        v0.z = c[i][2] + bcol[2]; v0.w = c[i][3] + bcol[3];
        v1.x = c[i][4] + bcol[4]; v1.y = c[i][5] + bcol[5];
        v1.z = c[i][6] + bcol[6]; v1.w = c[i][7] + bcol[7];
        *(float4*)(cp)     = v0;
        *(float4*)(cp + 4) = v1;
    }
}

// =========================================================================
// K2: per-(b,h) split-K Gram partials G = Qcols^T * Kcols over 1024 rows,
//     plus per-column sumsq partials (for L2 normalization). Deterministic.
// grid: (48 bh, 8 splits), 256 threads.
// =========================================================================
__global__ __launch_bounds__(256)
void gram_partial()
{
    const int bh = blockIdx.x;
    const int p  = blockIdx.y;
    const int b  = bh / NHEAD;
    const int h  = bh % NHEAD;

    __shared__ __align__(16) float Qs[16][HD];
    __shared__ __align__(16) float Ks[16][HD];

    const int t  = threadIdx.x;
    const int lr = t >> 4;           // 0..15 tile row
    const int lc = (t & 15) * 4;     // col quad
    const int tx = t & 15;
    const int ty = t >> 4;

    float c[4][4] = {};
    float sq = 0.0f;

    const size_t rowbase = (size_t)(b * SEQN + p * ROWS_PER_SPLIT) * C3;
    const int qcol = h * HD;

    for (int n0 = 0; n0 < ROWS_PER_SPLIT; n0 += 16) {
        const size_t base = rowbase + (size_t)(n0 + lr) * C3;
        *(float4*)&Qs[lr][lc] = *(const float4*)&g_Y[base + qcol + lc];
        *(float4*)&Ks[lr][lc] = *(const float4*)&g_Y[base + DIMC + qcol + lc];
        __syncthreads();

#pragma unroll
        for (int kk = 0; kk < 16; kk++) {
            float a[4], bb[4];
            *(float4*)a  = *(const float4*)&Qs[kk][ty * 4];
            *(float4*)bb = *(const float4*)&Ks[kk][tx * 4];
#pragma unroll
            for (int i = 0; i < 4; i++)
#pragma unroll
                for (int j = 0; j < 4; j++)
                    c[i][j] += a[i] * bb[j];
        }

        if (t < 64) {
#pragma unroll
            for (int kk = 0; kk < 16; kk++) { float v = Qs[kk][t]; sq += v * v; }
        } else if (t < 128) {
#pragma unroll
            for (int kk = 0; kk < 16; kk++) { float v = Ks[kk][t - 64]; sq += v * v; }
        }
        __syncthreads();
    }

    float* gp = &g_Gp[((size_t)bh * NSPLIT + p) * (HD * HD)];
#pragma unroll
    for (int i = 0; i < 4; i++)
#pragma unroll
        for (int j = 0; j < 4; j++)
            gp[(ty * 4 + i) * HD + tx * 4 + j] = c[i][j];

    if (t < 64) {
        g_Sqp[((size_t)b * NSPLIT + p) * (2 * DIMC) + h * HD + t] = sq;
    } else if (t < 128) {
        g_Sqp[((size_t)b * NSPLIT + p) * (2 * DIMC) + DIMC + h * HD + (t - 64)] = sq;
    }
}

// =========================================================================
// K3: reduce partials, scale by temperature / L2 norms, row softmax -> g_A.
// grid: 48 blocks, 256 threads.
// =========================================================================
__global__ __launch_bounds__(256)
void softmax_attn(const float* __restrict__ temperature)
{
    const int bh = blockIdx.x;
    const int b  = bh / NHEAD;
    const int h  = bh % NHEAD;
    const int t  = threadIdx.x;

    __shared__ float Gs[HD][HD + 1];
    __shared__ float rq[HD];
    __shared__ float rk[HD];

    const float* gp = &g_Gp[(size_t)bh * NSPLIT * (HD * HD)];
#pragma unroll
    for (int v = 0; v < 16; v++) {
        const int idx = t * 16 + v;
        float s = 0.0f;
#pragma unroll
        for (int p = 0; p < NSPLIT; p++) s += gp[p * (HD * HD) + idx];
        Gs[idx >> 6][idx & 63] = s;
    }

    if (t < 64) {
        float s = 0.0f;
#pragma unroll
        for (int p = 0; p < NSPLIT; p++)
            s += g_Sqp[((size_t)b * NSPLIT + p) * (2 * DIMC) + h * HD + t];
        rq[t] = temperature[h] / fmaxf(sqrtf(s), 1e-12f);
    } else if (t < 128) {
        const int e = t - 64;
        float s = 0.0f;
#pragma unroll
        for (int p = 0; p < NSPLIT; p++)
            s += g_Sqp[((size_t)b * NSPLIT + p) * (2 * DIMC) + DIMC + h * HD + e];
        rk[e] = 1.0f / fmaxf(sqrtf(s), 1e-12f);
    }
    __syncthreads();

    if (t < 64) {
        const int d = t;
        const float iq = rq[d];
        // pass 1: scale in place + max
        float mx = -1e30f;
        for (int e = 0; e < HD; e++) {
            const float v = Gs[d][e] * iq * rk[e];
            Gs[d][e] = v;
            mx = fmaxf(mx, v);
        }
        // pass 2: exp + sum
        float sum = 0.0f;
        for (int e = 0; e < HD; e++) {
            const float ex = expf(Gs[d][e] - mx);
            Gs[d][e] = ex;
            sum += ex;
        }
        const float inv = 1.0f / sum;
        float* ap = &g_A[(size_t)bh * (HD * HD) + d * HD];
        for (int e = 0; e < HD; e++) ap[e] = Gs[d][e] * inv;
    }
}

// =========================================================================
// K4: Weff[b][h*64+e][j] = sum_d A[b,h][d][e] * Wproj[h*64+d][j]
// grid: (6 j-tiles of 128, 48 bh), 256 threads.
// =========================================================================
__global__ __launch_bounds__(256)
void weff_kernel(const float* __restrict__ Wproj)
{
    const int jt = blockIdx.x;
    const int bh = blockIdx.y;
    const int b  = bh / NHEAD;
    const int h  = bh % NHEAD;
    const int t  = threadIdx.x;

    __shared__ __align__(16) float A_s[HD][HD];    // [d][e]  16 KB
    __shared__ __align__(16) float W_s[HD][128];   // [d][j]  32 KB

    const float* ap = &g_A[(size_t)bh * (HD * HD)];
#pragma unroll
    for (int v = 0; v < 4; v++) {
        const int idx = t * 16 + v * 4;
        *(float4*)&A_s[idx >> 6][idx & 63] = *(const float4*)&ap[idx];
    }

    const int jbase = jt * 128;
    const int wc  = (t & 31) * 4;
    const int wr0 = t >> 5;
#pragma unroll
    for (int rr = 0; rr < 8; rr++) {
        const int dr = wr0 + rr * 8;
        *(float4*)&W_s[dr][wc] =
            *(const float4*)&Wproj[(size_t)(h * HD + dr) * DIMC + jbase + wc];
    }
    __syncthreads();

    const int e0 = (t >> 5) * 8;
    const int j0 = (t & 31) * 4;
    float acc[8][4] = {};
#pragma unroll
    for (int d = 0; d < HD; d++) {
        float w[4];
        *(float4*)w = *(const float4*)&W_s[d][j0];
#pragma unroll
        for (int i = 0; i < 8; i++) {
            const float a = A_s[d][e0 + i];
#pragma unroll
            for (int j = 0; j < 4; j++) acc[i][j] += a * w[j];
        }
    }

    float* out = &g_Weff[((size_t)b * DIMC + h * HD) * DIMC + jbase];
#pragma unroll
    for (int i = 0; i < 8; i++)
        *(float4*)&out[(size_t)(e0 + i) * DIMC + j0] = *(float4*)acc[i];
}

// =========================================================================
extern "C" void kernel_launch(void* const* d_in, const int* in_sizes, int n_in,
                              void* d_out, int out_size)
{
    const float* x     = (const float*)d_in[0];
    const float* Wqkv  = (const float*)d_in[1];
    const float* bqkv  = (const float*)d_in[2];
    const float* temp  = (const float*)d_in[3];
    const float* Wproj = (const float*)d_in[4];
    const float* bproj = (const float*)d_in[5];
    float* out = (float*)d_out;

    // K1: Y = x @ Wqkv + bqkv   [32768 x 2304]
    sgemm_bias<0><<<dim3(C3 / 128, MROWS / 128), 256>>>(x, Wqkv, bqkv, nullptr);

    // K2: Gram + sumsq partials
    gram_partial<<<dim3(NBH, NSPLIT), 256>>>();

    // K3: reduce + scale + softmax -> A
    softmax_attn<<<NBH, 256>>>(temp);

    // K4: fold A into projection weight per batch
    weff_kernel<<<dim3(DIMC / 128, NBH), 256>>>(Wproj);

    // K5: Z = V @ Weff[b] + bproj   [32768 x 768]
    sgemm_bias<1><<<dim3(DIMC / 128, MROWS / 128), 256>>>(nullptr, nullptr, bproj, out);
}

// round 3
// speedup vs baseline: 1.6450x; 1.6450x over previous
#include <cuda_runtime.h>
#include <cstdint>
#include <math.h>

// Problem constants (fixed by reference setup)
#define DIMC   768
#define NHEAD  12
#define HD     64
#define BATCH  4
#define SEQN   8192
#define MROWS  (BATCH * SEQN)   // 32768
#define C3     (3 * DIMC)       // 2304
#define NSPLIT 8
#define ROWS_PER_SPLIT (SEQN / NSPLIT)  // 1024
#define NBH    (BATCH * NHEAD)  // 48

// ---------------- Device scratch (no cudaMalloc allowed) ----------------
__device__ float g_Y[(size_t)MROWS * C3];                 // qkv activations  (~302 MB)
__device__ float g_WqkvT[(size_t)C3 * DIMC];              // Wqkv transposed [2304][768]
__device__ float g_Gp[(size_t)NBH * NSPLIT * HD * HD];    // Gram partials
__device__ float g_Sqp[(size_t)BATCH * NSPLIT * 2 * DIMC];// col sumsq partials
__device__ float g_A[(size_t)NBH * HD * HD];              // softmaxed attention
__device__ float g_WeffT[(size_t)BATCH * DIMC * DIMC];    // folded proj weight, TRANSPOSED [j][k]

// ======================= mma.sync helpers =============================
__device__ __forceinline__ uint32_t f2tf32(float f) {
    uint32_t u;
    asm("cvt.rna.tf32.f32 %0, %1;" : "=r"(u) : "f"(f));
    return u;
}

__device__ __forceinline__ void mma_tf32(float* c,
                                         uint32_t a0, uint32_t a1, uint32_t a2, uint32_t a3,
                                         uint32_t b0, uint32_t b1) {
    asm volatile(
        "mma.sync.aligned.m16n8k8.row.col.f32.tf32.tf32.f32 "
        "{%0,%1,%2,%3}, {%4,%5,%6,%7}, {%8,%9}, {%0,%1,%2,%3};"
        : "+f"(c[0]), "+f"(c[1]), "+f"(c[2]), "+f"(c[3])
        : "r"(a0), "r"(a1), "r"(a2), "r"(a3), "r"(b0), "r"(b1));
}

// =========================================================================
// K1 / K5: tf32 mma.sync GEMM. CTA tile 128x128, BK=16, 8 warps (2m x 4n),
// warp tile 64x32 (4x4 m16n8k8 mmas), double-buffered SMEM, 1 sync/iter.
// MODE 0: Y = X @ Wqkv + bqkv     (A=Aext [M,768], B=g_WqkvT [2304,768])
// MODE 1: Z = V @ Weff[b] + bproj (A=g_Y+1536 ld 2304, B=g_WeffT per batch)
// SMEM bank engineering:
//   As[128][20]  (stride 20 = 4 mod 32): A-frag (8 rows x 4 k) -> 32 banks
//   Bs[16][136]  (stride 136 = 8 mod 32): B-frag (4 k x 8 n)   -> 32 banks
// =========================================================================
#define NKC (DIMC / 16)   // 48 K-chunks

template<int MODE>
__global__ void __launch_bounds__(256)
gemm_mma(const float* __restrict__ Aext,
         const float* __restrict__ bias,
         float* __restrict__ Cext)
{
    __shared__ __align__(16) uint32_t As[2][128][20];
    __shared__ __align__(16) uint32_t Bs[2][16][136];

    const int t    = threadIdx.x;
    const int lane = t & 31;
    const int warp = t >> 5;
    const int wm   = warp >> 2;          // 0..1 -> m offset 0/64
    const int wn   = warp & 3;           // 0..3 -> n offset 0/32/64/96
    const int qrow = lane >> 2;          // 0..7
    const int qcol = lane & 3;           // 0..3
    const int n0   = blockIdx.x * 128;
    const int m0   = blockIdx.y * 128;

    const float* A; const float* BT; float* C; int lda, ldc;
    if (MODE == 0) {
        A = Aext;           lda = DIMC;
        BT = g_WqkvT;       C = g_Y;   ldc = C3;
    } else {
        A = g_Y + 2 * DIMC; lda = C3;
        BT = g_WeffT + (size_t)(m0 / SEQN) * DIMC * DIMC;
        C = Cext;           ldc = DIMC;
    }

    // global load assignment: each thread owns one A row + one B row, half of BK
    const int am = t & 127;              // row within tile (A: m, B: n)
    const int kh = t >> 7;               // 0/1 -> k 0..7 / 8..15
    const float* Aptr = A  + (size_t)(m0 + am) * lda  + kh * 8;
    const float* Bptr = BT + (size_t)(n0 + am) * DIMC + kh * 8;

    float4 pa0, pa1, pb0, pb1;           // prefetch registers

    auto gload = [&](int kc) {
        const float* ap = Aptr + kc * 16;
        const float* bp = Bptr + kc * 16;
        pa0 = *(const float4*)(ap);
        pa1 = *(const float4*)(ap + 4);
        pb0 = *(const float4*)(bp);
        pb1 = *(const float4*)(bp + 4);
    };

    auto stile = [&](int buf) {
        uint4 u0, u1;
        u0.x = f2tf32(pa0.x); u0.y = f2tf32(pa0.y); u0.z = f2tf32(pa0.z); u0.w = f2tf32(pa0.w);
        u1.x = f2tf32(pa1.x); u1.y = f2tf32(pa1.y); u1.z = f2tf32(pa1.z); u1.w = f2tf32(pa1.w);
        *(uint4*)&As[buf][am][kh * 8]     = u0;
        *(uint4*)&As[buf][am][kh * 8 + 4] = u1;
        const int kb = kh * 8;
        Bs[buf][kb + 0][am] = f2tf32(pb0.x);
        Bs[buf][kb + 1][am] = f2tf32(pb0.y);
        Bs[buf][kb + 2][am] = f2tf32(pb0.z);
        Bs[buf][kb + 3][am] = f2tf32(pb0.w);
        Bs[buf][kb + 4][am] = f2tf32(pb1.x);
        Bs[buf][kb + 5][am] = f2tf32(pb1.y);
        Bs[buf][kb + 6][am] = f2tf32(pb1.z);
        Bs[buf][kb + 7][am] = f2tf32(pb1.w);
    };

    float acc[4][4][4] = {};

    gload(0);
    stile(0);
    __syncthreads();

    for (int kc = 0; kc < NKC; kc++) {
        if (kc + 1 < NKC) gload(kc + 1);

        const int buf = kc & 1;
#pragma unroll
        for (int ks = 0; ks < 2; ks++) {
            const int kb = ks * 8 + qcol;
            uint32_t bf0[4], bf1[4];
#pragma unroll
            for (int nj = 0; nj < 4; nj++) {
                const int n = wn * 32 + nj * 8 + qrow;
                bf0[nj] = Bs[buf][kb][n];
                bf1[nj] = Bs[buf][kb + 4][n];
            }
#pragma unroll
            for (int mi = 0; mi < 4; mi++) {
                const int r = wm * 64 + mi * 16 + qrow;
                const uint32_t a0 = As[buf][r][kb];
                const uint32_t a1 = As[buf][r + 8][kb];
                const uint32_t a2 = As[buf][r][kb + 4];
                const uint32_t a3 = As[buf][r + 8][kb + 4];
#pragma unroll
                for (int nj = 0; nj < 4; nj++)
                    mma_tf32(acc[mi][nj], a0, a1, a2, a3, bf0[nj], bf1[nj]);
            }
        }

        if (kc + 1 < NKC) stile((kc + 1) & 1);
        __syncthreads();
    }

    // ---- epilogue: +bias, direct global stores (float2 per fragment row) ----
#pragma unroll
    for (int mi = 0; mi < 4; mi++) {
        const int r = m0 + wm * 64 + mi * 16 + qrow;
#pragma unroll
        for (int nj = 0; nj < 4; nj++) {
            const int cI = n0 + wn * 32 + nj * 8 + qcol * 2;
            const float bv0 = bias[cI];
            const float bv1 = bias[cI + 1];
            float2 v0, v1;
            v0.x = acc[mi][nj][0] + bv0; v0.y = acc[mi][nj][1] + bv1;
            v1.x = acc[mi][nj][2] + bv0; v1.y = acc[mi][nj][3] + bv1;
            *(float2*)(C + (size_t)r * ldc + cI)       = v0;
            *(float2*)(C + (size_t)(r + 8) * ldc + cI) = v1;
        }
    }
}

// =========================================================================
// K0: transpose Wqkv [768,2304] -> g_WqkvT [2304,768]
// =========================================================================
__global__ __launch_bounds__(256)
void transpose_w(const float* __restrict__ W)
{
    __shared__ float tile[32][33];
    const int x = blockIdx.x * 32 + threadIdx.x;  // n in [0,2304)
    const int y = blockIdx.y * 32 + threadIdx.y;  // k base
#pragma unroll
    for (int i = 0; i < 32; i += 8)
        tile[threadIdx.y + i][threadIdx.x] = W[(size_t)(y + i) * C3 + x];
    __syncthreads();
    const int nx = blockIdx.y * 32 + threadIdx.x; // k
    const int ny = blockIdx.x * 32 + threadIdx.y; // n base
#pragma unroll
    for (int i = 0; i < 32; i += 8)
        g_WqkvT[(size_t)(ny + i) * DIMC + nx] = tile[threadIdx.x][threadIdx.y + i];
}

// =========================================================================
// K2: per-(b,h) split-K Gram partials + per-column sumsq partials.
// =========================================================================
__global__ __launch_bounds__(256)
void gram_partial()
{
    const int bh = blockIdx.x;
    const int p  = blockIdx.y;
    const int b  = bh / NHEAD;
    const int h  = bh % NHEAD;

    __shared__ __align__(16) float Qs[16][HD];
    __shared__ __align__(16) float Ks[16][HD];

    const int t  = threadIdx.x;
    const int lr = t >> 4;
    const int lc = (t & 15) * 4;
    const int tx = t & 15;
    const int ty = t >> 4;

    float c[4][4] = {};
    float sq = 0.0f;

    const size_t rowbase = (size_t)(b * SEQN + p * ROWS_PER_SPLIT) * C3;
    const int qcolb = h * HD;

    for (int n0 = 0; n0 < ROWS_PER_SPLIT; n0 += 16) {
        const size_t base = rowbase + (size_t)(n0 + lr) * C3;
        *(float4*)&Qs[lr][lc] = *(const float4*)&g_Y[base + qcolb + lc];
        *(float4*)&Ks[lr][lc] = *(const float4*)&g_Y[base + DIMC + qcolb + lc];
        __syncthreads();

#pragma unroll
        for (int kk = 0; kk < 16; kk++) {
            float a[4], bb[4];
            *(float4*)a  = *(const float4*)&Qs[kk][ty * 4];
            *(float4*)bb = *(const float4*)&Ks[kk][tx * 4];
#pragma unroll
            for (int i = 0; i < 4; i++)
#pragma unroll
                for (int j = 0; j < 4; j++)
                    c[i][j] += a[i] * bb[j];
        }

        if (t < 64) {
#pragma unroll
            for (int kk = 0; kk < 16; kk++) { float v = Qs[kk][t]; sq += v * v; }
        } else if (t < 128) {
#pragma unroll
            for (int kk = 0; kk < 16; kk++) { float v = Ks[kk][t - 64]; sq += v * v; }
        }
        __syncthreads();
    }

    float* gp = &g_Gp[((size_t)bh * NSPLIT + p) * (HD * HD)];
#pragma unroll
    for (int i = 0; i < 4; i++)
#pragma unroll
        for (int j = 0; j < 4; j++)
            gp[(ty * 4 + i) * HD + tx * 4 + j] = c[i][j];

    if (t < 64) {
        g_Sqp[((size_t)b * NSPLIT + p) * (2 * DIMC) + h * HD + t] = sq;
    } else if (t < 128) {
        g_Sqp[((size_t)b * NSPLIT + p) * (2 * DIMC) + DIMC + h * HD + (t - 64)] = sq;
    }
}

// =========================================================================
// K3: reduce partials, scale, row softmax -> g_A
// =========================================================================
__global__ __launch_bounds__(256)
void softmax_attn(const float* __restrict__ temperature)
{
    const int bh = blockIdx.x;
    const int b  = bh / NHEAD;
    const int h  = bh % NHEAD;
    const int t  = threadIdx.x;

    __shared__ float Gs[HD][HD + 1];
    __shared__ float rq[HD];
    __shared__ float rk[HD];

    const float* gp = &g_Gp[(size_t)bh * NSPLIT * (HD * HD)];
#pragma unroll
    for (int v = 0; v < 16; v++) {
        const int idx = t * 16 + v;
        float s = 0.0f;
#pragma unroll
        for (int p = 0; p < NSPLIT; p++) s += gp[p * (HD * HD) + idx];
        Gs[idx >> 6][idx & 63] = s;
    }

    if (t < 64) {
        float s = 0.0f;
#pragma unroll
        for (int p = 0; p < NSPLIT; p++)
            s += g_Sqp[((size_t)b * NSPLIT + p) * (2 * DIMC) + h * HD + t];
        rq[t] = temperature[h] / fmaxf(sqrtf(s), 1e-12f);
    } else if (t < 128) {
        const int e = t - 64;
        float s = 0.0f;
#pragma unroll
        for (int p = 0; p < NSPLIT; p++)
            s += g_Sqp[((size_t)b * NSPLIT + p) * (2 * DIMC) + DIMC + h * HD + e];
        rk[e] = 1.0f / fmaxf(sqrtf(s), 1e-12f);
    }
    __syncthreads();

    if (t < 64) {
        const int d = t;
        const float iq = rq[d];
        float mx = -1e30f;
        for (int e = 0; e < HD; e++) {
            const float v = Gs[d][e] * iq * rk[e];
            Gs[d][e] = v;
            mx = fmaxf(mx, v);
        }
        float sum = 0.0f;
        for (int e = 0; e < HD; e++) {
            const float ex = expf(Gs[d][e] - mx);
            Gs[d][e] = ex;
            sum += ex;
        }
        const float inv = 1.0f / sum;
        float* ap = &g_A[(size_t)bh * (HD * HD) + d * HD];
        for (int e = 0; e < HD; e++) ap[e] = Gs[d][e] * inv;
    }
}

// =========================================================================
// K4: WeffT[b][j][h*64+e] = sum_d A[b,h][d][e] * Wproj[h*64+d][j]
// =========================================================================
__global__ __launch_bounds__(256)
void weff_kernel(const float* __restrict__ Wproj)
{
    const int jt = blockIdx.x;
    const int bh = blockIdx.y;
    const int b  = bh / NHEAD;
    const int h  = bh % NHEAD;
    const int t  = threadIdx.x;

    __shared__ __align__(16) float A_s[HD][HD];
    __shared__ __align__(16) float W_s[HD][128];

    const float* ap = &g_A[(size_t)bh * (HD * HD)];
#pragma unroll
    for (int v = 0; v < 4; v++) {
        const int idx = t * 16 + v * 4;
        *(float4*)&A_s[idx >> 6][idx & 63] = *(const float4*)&ap[idx];
    }

    const int jbase = jt * 128;
    const int wc  = (t & 31) * 4;
    const int wr0 = t >> 5;
#pragma unroll
    for (int rr = 0; rr < 8; rr++) {
        const int dr = wr0 + rr * 8;
        *(float4*)&W_s[dr][wc] =
            *(const float4*)&Wproj[(size_t)(h * HD + dr) * DIMC + jbase + wc];
    }
    __syncthreads();

    const int e0 = (t >> 5) * 8;
    const int j0 = (t & 31) * 4;
    float acc[8][4] = {};
#pragma unroll
    for (int d = 0; d < HD; d++) {
        float w[4];
        *(float4*)w = *(const float4*)&W_s[d][j0];
#pragma unroll
        for (int i = 0; i < 8; i++) {
            const float a = A_s[d][e0 + i];
#pragma unroll
            for (int j = 0; j < 4; j++) acc[i][j] += a * w[j];
        }
    }

    // transposed write: row = global j, col = h*64 + e
    float* outT = &g_WeffT[(size_t)b * DIMC * DIMC + (size_t)jbase * DIMC + h * HD];
#pragma unroll
    for (int i = 0; i < 8; i++)
#pragma unroll
        for (int j = 0; j < 4; j++)
            outT[(size_t)(j0 + j) * DIMC + (e0 + i)] = acc[i][j];
}

// =========================================================================
extern "C" void kernel_launch(void* const* d_in, const int* in_sizes, int n_in,
                              void* d_out, int out_size)
{
    const float* x     = (const float*)d_in[0];
    const float* Wqkv  = (const float*)d_in[1];
    const float* bqkv  = (const float*)d_in[2];
    const float* temp  = (const float*)d_in[3];
    const float* Wproj = (const float*)d_in[4];
    const float* bproj = (const float*)d_in[5];
    float* out = (float*)d_out;

    // K0: transpose Wqkv -> K-major B
    transpose_w<<<dim3(C3 / 32, DIMC / 32), dim3(32, 8)>>>(Wqkv);

    // K1: Y = x @ Wqkv + bqkv   [32768 x 2304], tf32 mma.sync
    gemm_mma<0><<<dim3(C3 / 128, MROWS / 128), 256>>>(x, bqkv, nullptr);

    // K2: Gram + sumsq partials
    gram_partial<<<dim3(NBH, NSPLIT), 256>>>();

    // K3: reduce + scale + softmax -> A
    softmax_attn<<<NBH, 256>>>(temp);

    // K4: fold A into projection weight per batch (transposed output)
    weff_kernel<<<dim3(DIMC / 128, NBH), 256>>>(Wproj);

    // K5: Z = V @ Weff[b] + bproj   [32768 x 768], tf32 mma.sync
    gemm_mma<1><<<dim3(DIMC / 128, MROWS / 128), 256>>>(nullptr, bproj, out);
}

// round 4
// speedup vs baseline: 2.2909x; 1.3927x over previous
#include <cuda_runtime.h>
#include <cstdint>
#include <math.h>

// Problem constants (fixed by reference setup)
#define DIMC   768
#define NHEAD  12
#define HD     64
#define BATCH  4
#define SEQN   8192
#define MROWS  (BATCH * SEQN)   // 32768
#define C3     (3 * DIMC)       // 2304
#define NSPLIT 8
#define ROWS_PER_SPLIT (SEQN / NSPLIT)  // 1024
#define NBH    (BATCH * NHEAD)  // 48

// ---------------- Device scratch (no cudaMalloc allowed) ----------------
__device__ float g_Y[(size_t)MROWS * C3];                 // qkv activations (V part stored as tf32 bits)
__device__ float g_Xc[(size_t)MROWS * DIMC];              // x pre-converted to tf32 bits
__device__ float g_WqkvT[(size_t)C3 * DIMC];              // Wqkv transposed, tf32 bits
__device__ float g_Gp[(size_t)NBH * NSPLIT * HD * HD];    // Gram partials
__device__ float g_Sqp[(size_t)BATCH * NSPLIT * 2 * DIMC];// col sumsq partials
__device__ float g_A[(size_t)NBH * HD * HD];              // softmaxed attention
__device__ float g_WeffT[(size_t)BATCH * DIMC * DIMC];    // folded proj weight, transposed, tf32 bits

// ======================= helpers =============================
__device__ __forceinline__ uint32_t f2tf32(float f) {
    uint32_t u;
    asm("cvt.rna.tf32.f32 %0, %1;" : "=r"(u) : "f"(f));
    return u;
}

__device__ __forceinline__ void mma_tf32(float* c,
                                         uint32_t a0, uint32_t a1, uint32_t a2, uint32_t a3,
                                         uint32_t b0, uint32_t b1) {
    asm volatile(
        "mma.sync.aligned.m16n8k8.row.col.f32.tf32.tf32.f32 "
        "{%0,%1,%2,%3}, {%4,%5,%6,%7}, {%8,%9}, {%0,%1,%2,%3};"
        : "+f"(c[0]), "+f"(c[1]), "+f"(c[2]), "+f"(c[3])
        : "r"(a0), "r"(a1), "r"(a2), "r"(a3), "r"(b0), "r"(b1));
}

__device__ __forceinline__ uint32_t smem_u32(const void* p) {
    uint32_t a;
    asm("{ .reg .u64 t; cvta.to.shared.u64 t, %1; cvt.u32.u64 %0, t; }"
        : "=r"(a) : "l"(p));
    return a;
}

__device__ __forceinline__ void cp16(uint32_t dst, const void* src) {
    asm volatile("cp.async.cg.shared.global [%0], [%1], 16;"
                 :: "r"(dst), "l"(src) : "memory");
}
__device__ __forceinline__ void cp_commit() {
    asm volatile("cp.async.commit_group;" ::: "memory");
}
template<int N>
__device__ __forceinline__ void cp_wait() {
    asm volatile("cp.async.wait_group %0;" :: "n"(N) : "memory");
}

// =========================================================================
// K1 / K5: tf32 mma.sync GEMM, inputs pre-converted to tf32 bit patterns.
// CTA tile 128x128, BK=32, 3-stage cp.async pipeline, 8 warps (2m x 4n),
// warp tile 64x32 (4x4 m16n8k8). SMEM tiles [128][36] row-major:
// stride 36 = 4 (mod 32) -> fragment reads (qrow*4+qcol) hit 32 distinct banks.
// MODE 0: Y = Xc @ WqkvT + bqkv  (V-region output stored as tf32 bits)
// MODE 1: Z = V @ WeffT[b] + bproj
// =========================================================================
#define BKQ     32
#define NKC     (DIMC / BKQ)     // 24
#define SP      36               // padded row stride (floats)
#define ATILE   (128 * SP)       // 4608 floats per tile
#define STAGEF  (2 * ATILE)      // A + B per stage
#define GSMEM   (3 * STAGEF * 4) // 110592 bytes

template<int MODE>
__global__ void __launch_bounds__(256)
gemm_cp(const float* __restrict__ Aext,
        const float* __restrict__ bias,
        float* __restrict__ Cext)
{
    extern __shared__ __align__(16) float smem[];
    const uint32_t sbase = smem_u32(smem);

    const int t    = threadIdx.x;
    const int lane = t & 31;
    const int warp = t >> 5;
    const int wm   = warp >> 2;          // 0..1 -> m offset 0/64
    const int wn   = warp & 3;           // 0..3 -> n offset 0/32/64/96
    const int qrow = lane >> 2;          // 0..7
    const int qcol = lane & 3;           // 0..3
    const int n0   = blockIdx.x * 128;
    const int m0   = blockIdx.y * 128;

    const float* A; const float* BT; float* C; int lda, ldc;
    if (MODE == 0) {
        A = g_Xc;           lda = DIMC;
        BT = g_WqkvT;       C = g_Y;   ldc = C3;
    } else {
        A = g_Y + 2 * DIMC; lda = C3;
        BT = g_WeffT + (size_t)(m0 / SEQN) * DIMC * DIMC;
        C = Cext;           ldc = DIMC;
    }

    // cp.async assignment: 2 threads per row, 16 floats each
    const int lrow  = t >> 1;            // 0..127
    const int khalf = (t & 1) * 16;      // 0 or 16
    const float* Ap = A  + (size_t)(m0 + lrow) * lda  + khalf;
    const float* Bp = BT + (size_t)(n0 + lrow) * DIMC + khalf;
    const uint32_t sOffA = (uint32_t)(lrow * SP + khalf) * 4;

    auto issue = [&](int kc) {
        const int s = kc % 3;
        const uint32_t dA = sbase + (uint32_t)(s * STAGEF) * 4 + sOffA;
        const uint32_t dB = dA + (uint32_t)ATILE * 4;
        const float* ga = Ap + kc * BKQ;
        const float* gb = Bp + kc * BKQ;
#pragma unroll
        for (int j = 0; j < 4; j++) {
            cp16(dA + j * 16, ga + j * 4);
            cp16(dB + j * 16, gb + j * 4);
        }
    };

    issue(0); cp_commit();
    issue(1); cp_commit();

    float acc[4][4][4] = {};

    for (int kc = 0; kc < NKC; kc++) {
        cp_wait<1>();          // stage kc landed (this thread's groups)
        __syncthreads();       // visible to all
        if (kc + 2 < NKC) issue(kc + 2);
        cp_commit();           // always commit to keep group count uniform

        const uint32_t* Asm = (const uint32_t*)(smem + (kc % 3) * STAGEF);
        const uint32_t* Bsm = Asm + ATILE;

#pragma unroll
        for (int ks = 0; ks < 4; ks++) {
            const int kb = ks * 8 + qcol;
            uint32_t bf0[4], bf1[4];
#pragma unroll
            for (int nj = 0; nj < 4; nj++) {
                const int n = wn * 32 + nj * 8 + qrow;
                bf0[nj] = Bsm[n * SP + kb];
                bf1[nj] = Bsm[n * SP + kb + 4];
            }
#pragma unroll
            for (int mi = 0; mi < 4; mi++) {
                const int r = wm * 64 + mi * 16 + qrow;
                const uint32_t a0 = Asm[r * SP + kb];
                const uint32_t a1 = Asm[(r + 8) * SP + kb];
                const uint32_t a2 = Asm[r * SP + kb + 4];
                const uint32_t a3 = Asm[(r + 8) * SP + kb + 4];
#pragma unroll
                for (int nj = 0; nj < 4; nj++)
                    mma_tf32(acc[mi][nj], a0, a1, a2, a3, bf0[nj], bf1[nj]);
            }
        }
        __syncthreads();       // stage kc fully consumed before reuse
    }

    // ---- epilogue: +bias; MODE 0 V-region (n0 >= 1536) stored as tf32 bits ----
    const bool cvtV = (MODE == 0) && (n0 >= 2 * DIMC);
#pragma unroll
    for (int mi = 0; mi < 4; mi++) {
        const int r = m0 + wm * 64 + mi * 16 + qrow;
#pragma unroll
        for (int nj = 0; nj < 4; nj++) {
            const int cI = n0 + wn * 32 + nj * 8 + qcol * 2;
            const float bv0 = bias[cI];
            const float bv1 = bias[cI + 1];
            float2 v0, v1;
            v0.x = acc[mi][nj][0] + bv0; v0.y = acc[mi][nj][1] + bv1;
            v1.x = acc[mi][nj][2] + bv0; v1.y = acc[mi][nj][3] + bv1;
            if (cvtV) {
                v0.x = __uint_as_float(f2tf32(v0.x)); v0.y = __uint_as_float(f2tf32(v0.y));
                v1.x = __uint_as_float(f2tf32(v1.x)); v1.y = __uint_as_float(f2tf32(v1.y));
            }
            *(float2*)(C + (size_t)r * ldc + cI)       = v0;
            *(float2*)(C + (size_t)(r + 8) * ldc + cI) = v1;
        }
    }
}

// =========================================================================
// K-1: pre-convert x to tf32 bit patterns
// =========================================================================
__global__ __launch_bounds__(256)
void convert_x(const float* __restrict__ x)
{
    const size_t i = ((size_t)blockIdx.x * 256 + threadIdx.x) * 4;
    if (i >= (size_t)MROWS * DIMC) return;
    float4 v = *(const float4*)(x + i);
    v.x = __uint_as_float(f2tf32(v.x));
    v.y = __uint_as_float(f2tf32(v.y));
    v.z = __uint_as_float(f2tf32(v.z));
    v.w = __uint_as_float(f2tf32(v.w));
    *(float4*)(g_Xc + i) = v;
}

// =========================================================================
// K0: transpose Wqkv [768,2304] -> g_WqkvT [2304,768], tf32-converted
// =========================================================================
__global__ __launch_bounds__(256)
void transpose_w(const float* __restrict__ W)
{
    __shared__ float tile[32][33];
    const int x = blockIdx.x * 32 + threadIdx.x;  // n in [0,2304)
    const int y = blockIdx.y * 32 + threadIdx.y;  // k base
#pragma unroll
    for (int i = 0; i < 32; i += 8)
        tile[threadIdx.y + i][threadIdx.x] = W[(size_t)(y + i) * C3 + x];
    __syncthreads();
    const int nx = blockIdx.y * 32 + threadIdx.x; // k
    const int ny = blockIdx.x * 32 + threadIdx.y; // n base
#pragma unroll
    for (int i = 0; i < 32; i += 8)
        g_WqkvT[(size_t)(ny + i) * DIMC + nx] =
            __uint_as_float(f2tf32(tile[threadIdx.x][threadIdx.y + i]));
}

// =========================================================================
// K2: per-(b,h) split-K Gram partials + per-column sumsq partials (fp32).
// =========================================================================
__global__ __launch_bounds__(256)
void gram_partial()
{
    const int bh = blockIdx.x;
    const int p  = blockIdx.y;
    const int b  = bh / NHEAD;
    const int h  = bh % NHEAD;

    __shared__ __align__(16) float Qs[16][HD];
    __shared__ __align__(16) float Ks[16][HD];

    const int t  = threadIdx.x;
    const int lr = t >> 4;
    const int lc = (t & 15) * 4;
    const int tx = t & 15;
    const int ty = t >> 4;

    float c[4][4] = {};
    float sq = 0.0f;

    const size_t rowbase = (size_t)(b * SEQN + p * ROWS_PER_SPLIT) * C3;
    const int qcolb = h * HD;

    for (int n0 = 0; n0 < ROWS_PER_SPLIT; n0 += 16) {
        const size_t base = rowbase + (size_t)(n0 + lr) * C3;
        *(float4*)&Qs[lr][lc] = *(const float4*)&g_Y[base + qcolb + lc];
        *(float4*)&Ks[lr][lc] = *(const float4*)&g_Y[base + DIMC + qcolb + lc];
        __syncthreads();

#pragma unroll
        for (int kk = 0; kk < 16; kk++) {
            float a[4], bb[4];
            *(float4*)a  = *(const float4*)&Qs[kk][ty * 4];
            *(float4*)bb = *(const float4*)&Ks[kk][tx * 4];
#pragma unroll
            for (int i = 0; i < 4; i++)
#pragma unroll
                for (int j = 0; j < 4; j++)
                    c[i][j] += a[i] * bb[j];
        }

        if (t < 64) {
#pragma unroll
            for (int kk = 0; kk < 16; kk++) { float v = Qs[kk][t]; sq += v * v; }
        } else if (t < 128) {
#pragma unroll
            for (int kk = 0; kk < 16; kk++) { float v = Ks[kk][t - 64]; sq += v * v; }
        }
        __syncthreads();
    }

    float* gp = &g_Gp[((size_t)bh * NSPLIT + p) * (HD * HD)];
#pragma unroll
    for (int i = 0; i < 4; i++)
#pragma unroll
        for (int j = 0; j < 4; j++)
            gp[(ty * 4 + i) * HD + tx * 4 + j] = c[i][j];

    if (t < 64) {
        g_Sqp[((size_t)b * NSPLIT + p) * (2 * DIMC) + h * HD + t] = sq;
    } else if (t < 128) {
        g_Sqp[((size_t)b * NSPLIT + p) * (2 * DIMC) + DIMC + h * HD + (t - 64)] = sq;
    }
}

// =========================================================================
// K3: reduce partials, scale, row softmax -> g_A
// =========================================================================
__global__ __launch_bounds__(256)
void softmax_attn(const float* __restrict__ temperature)
{
    const int bh = blockIdx.x;
    const int b  = bh / NHEAD;
    const int h  = bh % NHEAD;
    const int t  = threadIdx.x;

    __shared__ float Gs[HD][HD + 1];
    __shared__ float rq[HD];
    __shared__ float rk[HD];

    const float* gp = &g_Gp[(size_t)bh * NSPLIT * (HD * HD)];
#pragma unroll
    for (int v = 0; v < 16; v++) {
        const int idx = t * 16 + v;
        float s = 0.0f;
#pragma unroll
        for (int p = 0; p < NSPLIT; p++) s += gp[p * (HD * HD) + idx];
        Gs[idx >> 6][idx & 63] = s;
    }

    if (t < 64) {
        float s = 0.0f;
#pragma unroll
        for (int p = 0; p < NSPLIT; p++)
            s += g_Sqp[((size_t)b * NSPLIT + p) * (2 * DIMC) + h * HD + t];
        rq[t] = temperature[h] / fmaxf(sqrtf(s), 1e-12f);
    } else if (t < 128) {
        const int e = t - 64;
        float s = 0.0f;
#pragma unroll
        for (int p = 0; p < NSPLIT; p++)
            s += g_Sqp[((size_t)b * NSPLIT + p) * (2 * DIMC) + DIMC + h * HD + e];
        rk[e] = 1.0f / fmaxf(sqrtf(s), 1e-12f);
    }
    __syncthreads();

    if (t < 64) {
        const int d = t;
        const float iq = rq[d];
        float mx = -1e30f;
        for (int e = 0; e < HD; e++) {
            const float v = Gs[d][e] * iq * rk[e];
            Gs[d][e] = v;
            mx = fmaxf(mx, v);
        }
        float sum = 0.0f;
        for (int e = 0; e < HD; e++) {
            const float ex = expf(Gs[d][e] - mx);
            Gs[d][e] = ex;
            sum += ex;
        }
        const float inv = 1.0f / sum;
        float* ap = &g_A[(size_t)bh * (HD * HD) + d * HD];
        for (int e = 0; e < HD; e++) ap[e] = Gs[d][e] * inv;
    }
}

// =========================================================================
// K4: WeffT[b][j][h*64+e] = sum_d A[b,h][d][e] * Wproj[h*64+d][j]  (tf32 out)
// =========================================================================
__global__ __launch_bounds__(256)
void weff_kernel(const float* __restrict__ Wproj)
{
    const int jt = blockIdx.x;
    const int bh = blockIdx.y;
    const int b  = bh / NHEAD;
    const int h  = bh % NHEAD;
    const int t  = threadIdx.x;

    __shared__ __align__(16) float A_s[HD][HD];
    __shared__ __align__(16) float W_s[HD][128];

    const float* ap = &g_A[(size_t)bh * (HD * HD)];
#pragma unroll
    for (int v = 0; v < 4; v++) {
        const int idx = t * 16 + v * 4;
        *(float4*)&A_s[idx >> 6][idx & 63] = *(const float4*)&ap[idx];
    }

    const int jbase = jt * 128;
    const int wc  = (t & 31) * 4;
    const int wr0 = t >> 5;
#pragma unroll
    for (int rr = 0; rr < 8; rr++) {
        const int dr = wr0 + rr * 8;
        *(float4*)&W_s[dr][wc] =
            *(const float4*)&Wproj[(size_t)(h * HD + dr) * DIMC + jbase + wc];
    }
    __syncthreads();

    const int e0 = (t >> 5) * 8;
    const int j0 = (t & 31) * 4;
    float acc[8][4] = {};
#pragma unroll
    for (int d = 0; d < HD; d++) {
        float w[4];
        *(float4*)w = *(const float4*)&W_s[d][j0];
#pragma unroll
        for (int i = 0; i < 8; i++) {
            const float a = A_s[d][e0 + i];
#pragma unroll
            for (int j = 0; j < 4; j++) acc[i][j] += a * w[j];
        }
    }

    // transposed write: row = global j, col = h*64 + e  (tf32 bit patterns)
    float* outT = &g_WeffT[(size_t)b * DIMC * DIMC + (size_t)jbase * DIMC + h * HD];
#pragma unroll
    for (int i = 0; i < 8; i++)
#pragma unroll
        for (int j = 0; j < 4; j++)
            outT[(size_t)(j0 + j) * DIMC + (e0 + i)] =
                __uint_as_float(f2tf32(acc[i][j]));
}

// =========================================================================
extern "C" void kernel_launch(void* const* d_in, const int* in_sizes, int n_in,
                              void* d_out, int out_size)
{
    const float* x     = (const float*)d_in[0];
    const float* Wqkv  = (const float*)d_in[1];
    const float* bqkv  = (const float*)d_in[2];
    const float* temp  = (const float*)d_in[3];
    const float* Wproj = (const float*)d_in[4];
    const float* bproj = (const float*)d_in[5];
    float* out = (float*)d_out;

    cudaFuncSetAttribute(gemm_cp<0>, cudaFuncAttributeMaxDynamicSharedMemorySize, GSMEM);
    cudaFuncSetAttribute(gemm_cp<1>, cudaFuncAttributeMaxDynamicSharedMemorySize, GSMEM);

    // K-1: pre-convert x to tf32 bits
    convert_x<<<(MROWS * DIMC / 4 + 255) / 256, 256>>>(x);

    // K0: transpose + convert Wqkv -> K-major tf32 B
    transpose_w<<<dim3(C3 / 32, DIMC / 32), dim3(32, 8)>>>(Wqkv);

    // K1: Y = Xc @ WqkvT + bqkv   [32768 x 2304]
    gemm_cp<0><<<dim3(C3 / 128, MROWS / 128), 256, GSMEM>>>(nullptr, bqkv, nullptr);

    // K2: Gram + sumsq partials
    gram_partial<<<dim3(NBH, NSPLIT), 256>>>();

    // K3: reduce + scale + softmax -> A
    softmax_attn<<<NBH, 256>>>(temp);

    // K4: fold A into projection weight per batch (transposed tf32 output)
    weff_kernel<<<dim3(DIMC / 128, NBH), 256>>>(Wproj);

    // K5: Z = V @ WeffT[b] + bproj   [32768 x 768]
    gemm_cp<1><<<dim3(DIMC / 128, MROWS / 128), 256, GSMEM>>>(nullptr, bproj, out);
}

// round 5
// speedup vs baseline: 4.5709x; 1.9952x over previous
#include <cuda_runtime.h>
#include <cuda_fp16.h>
#include <cstdint>
#include <math.h>

// Problem constants (fixed by reference setup)
#define DIMC   768
#define NHEAD  12
#define HD     64
#define BATCH  4
#define SEQN   8192
#define MROWS  (BATCH * SEQN)   // 32768
#define C3     (3 * DIMC)       // 2304
#define NSPLIT 16
#define RPS    (SEQN / NSPLIT)  // 512 rows per split
#define NBH    (BATCH * NHEAD)  // 48

// ---------------- Device scratch (no cudaMalloc allowed) ----------------
__device__ __half g_Yh[(size_t)MROWS * C3];                // qkv activations, fp16 (~151 MB)
__device__ __half g_Xh[(size_t)MROWS * DIMC];              // x in fp16
__device__ __half g_WqkvTh[(size_t)C3 * DIMC];             // Wqkv^T fp16
__device__ __half g_WeffTh[(size_t)BATCH * DIMC * DIMC];   // folded proj weight^T fp16
__device__ float  g_Gp[(size_t)NBH * NSPLIT * HD * HD];    // Gram partials
__device__ float  g_Sqp[(size_t)BATCH * NSPLIT * 2 * DIMC];// col sumsq partials
__device__ float  g_A[(size_t)NBH * HD * HD];              // softmaxed attention

// ======================= PTX helpers =============================
__device__ __forceinline__ uint32_t smem_u32(const void* p) {
    uint32_t a;
    asm("{ .reg .u64 t; cvta.to.shared.u64 t, %1; cvt.u32.u64 %0, t; }"
        : "=r"(a) : "l"(p));
    return a;
}
__device__ __forceinline__ void cp16(uint32_t dst, const void* src) {
    asm volatile("cp.async.cg.shared.global [%0], [%1], 16;"
                 :: "r"(dst), "l"(src) : "memory");
}
__device__ __forceinline__ void cp_commit() {
    asm volatile("cp.async.commit_group;" ::: "memory");
}
template<int N>
__device__ __forceinline__ void cp_wait() {
    asm volatile("cp.async.wait_group %0;" :: "n"(N) : "memory");
}
__device__ __forceinline__ void ldsm4(uint32_t& r0, uint32_t& r1, uint32_t& r2,
                                      uint32_t& r3, uint32_t addr) {
    asm volatile("ldmatrix.sync.aligned.m8n8.x4.shared.b16 {%0,%1,%2,%3}, [%4];"
                 : "=r"(r0), "=r"(r1), "=r"(r2), "=r"(r3) : "r"(addr));
}
__device__ __forceinline__ void ldsm4t(uint32_t& r0, uint32_t& r1, uint32_t& r2,
                                       uint32_t& r3, uint32_t addr) {
    asm volatile("ldmatrix.sync.aligned.m8n8.x4.trans.shared.b16 {%0,%1,%2,%3}, [%4];"
                 : "=r"(r0), "=r"(r1), "=r"(r2), "=r"(r3) : "r"(addr));
}
__device__ __forceinline__ void mma16(float* c, const uint32_t* a,
                                      uint32_t b0, uint32_t b1) {
    asm volatile(
        "mma.sync.aligned.m16n8k16.row.col.f32.f16.f16.f32 "
        "{%0,%1,%2,%3}, {%4,%5,%6,%7}, {%8,%9}, {%0,%1,%2,%3};"
        : "+f"(c[0]), "+f"(c[1]), "+f"(c[2]), "+f"(c[3])
        : "r"(a[0]), "r"(a[1]), "r"(a[2]), "r"(a[3]), "r"(b0), "r"(b1));
}

// =========================================================================
// K1 / K5: fp16 mma.sync GEMM. CTA tile 128x128, BK=32 halves, 3-stage
// cp.async pipeline, 8 warps (2m x 4n), warp tile 64x32, m16n8k16 frags
// via ldmatrix. SMEM tiles [128][40] halves (stride 20 words: ldmatrix
// row addresses hit distinct banks).
// MODE 0: Yh = Xh @ WqkvTh + bqkv  -> g_Yh (fp16)
// MODE 1: Z  = Vh @ WeffTh[b] + bproj -> out (fp32)
// =========================================================================
#define BKH    32
#define NKC    (DIMC / BKH)      // 24
#define SPH    40                // padded row stride (halves)
#define TILEH  (128 * SPH)       // halves per tile
#define STAGEH (2 * TILEH)       // A + B per stage (halves)
#define GSMEM  (3 * STAGEH * 2)  // 61440 bytes

template<int MODE>
__global__ void __launch_bounds__(256)
gemm_h(const float* __restrict__ bias, float* __restrict__ Cext)
{
    extern __shared__ __align__(16) __half smem[];
    const uint32_t sbase = smem_u32(smem);

    const int t    = threadIdx.x;
    const int lane = t & 31;
    const int warp = t >> 5;
    const int wm   = warp >> 2;          // 0..1 -> m offset 0/64
    const int wn   = warp & 3;           // 0..3 -> n offset 0/32/64/96
    const int qrow = lane >> 2;
    const int qcol = lane & 3;
    const int n0   = blockIdx.x * 128;
    const int m0   = blockIdx.y * 128;

    const __half* A; const __half* BT; int lda;
    if (MODE == 0) {
        A  = g_Xh;            lda = DIMC;
        BT = g_WqkvTh;
    } else {
        A  = g_Yh + 2 * DIMC; lda = C3;   // V columns
        BT = g_WeffTh + (size_t)(m0 / SEQN) * DIMC * DIMC;
    }

    // cp.async: 2 threads per row, 16 halves (32B) each, 2x 16B chunks
    const int lrow = t >> 1;             // 0..127
    const int kseg = (t & 1) * 16;       // half offset within BK
    const __half* Ap = A  + (size_t)(m0 + lrow) * lda  + kseg;
    const __half* Bp = BT + (size_t)(n0 + lrow) * DIMC + kseg;
    const uint32_t sOff = (uint32_t)(lrow * SPH + kseg) * 2;

    auto issue = [&](int kc) {
        const uint32_t dA = sbase + (uint32_t)((kc % 3) * STAGEH) * 2 + sOff;
        const uint32_t dB = dA + (uint32_t)TILEH * 2;
        const __half* ga = Ap + kc * BKH;
        const __half* gb = Bp + kc * BKH;
        cp16(dA,      ga);
        cp16(dA + 16, ga + 8);
        cp16(dB,      gb);
        cp16(dB + 16, gb + 8);
    };

    issue(0); cp_commit();
    issue(1); cp_commit();

    float acc[4][4][4] = {};

    // ldmatrix lane address components
    const int rsel = (lane & 7) + ((lane >> 3) & 1) * 8;  // row within 16
    const int ksel = ((lane >> 4) & 1) * 8;               // k half-offset

    for (int kc = 0; kc < NKC; kc++) {
        cp_wait<1>();
        __syncthreads();
        if (kc + 2 < NKC) issue(kc + 2);
        cp_commit();

        const uint32_t aBase = sbase + (uint32_t)((kc % 3) * STAGEH) * 2;
        const uint32_t bBase = aBase + (uint32_t)TILEH * 2;

#pragma unroll
        for (int ks = 0; ks < 2; ks++) {
            const int koff = ks * 16 + ksel;
            uint32_t a[4][4];
#pragma unroll
            for (int mi = 0; mi < 4; mi++) {
                const int row = wm * 64 + mi * 16 + rsel;
                ldsm4(a[mi][0], a[mi][1], a[mi][2], a[mi][3],
                      aBase + (uint32_t)(row * SPH + koff) * 2);
            }
            uint32_t b0[4], b1[4];
#pragma unroll
            for (int p = 0; p < 2; p++) {
                uint32_t r0, r1, r2, r3;
                const int row = wn * 32 + p * 16 + rsel;
                ldsm4(r0, r1, r2, r3, bBase + (uint32_t)(row * SPH + koff) * 2);
                b0[2 * p] = r0; b1[2 * p] = r2;       // n-tile 2p
                b0[2 * p + 1] = r1; b1[2 * p + 1] = r3; // n-tile 2p+1
            }
#pragma unroll
            for (int mi = 0; mi < 4; mi++)
#pragma unroll
                for (int nj = 0; nj < 4; nj++)
                    mma16(acc[mi][nj], a[mi], b0[nj], b1[nj]);
        }
    }

    // ---- epilogue ----
#pragma unroll
    for (int mi = 0; mi < 4; mi++) {
        const int r = m0 + wm * 64 + mi * 16 + qrow;
#pragma unroll
        for (int nj = 0; nj < 4; nj++) {
            const int cI = n0 + wn * 32 + nj * 8 + qcol * 2;
            const float bv0 = bias[cI];
            const float bv1 = bias[cI + 1];
            const float v00 = acc[mi][nj][0] + bv0, v01 = acc[mi][nj][1] + bv1;
            const float v10 = acc[mi][nj][2] + bv0, v11 = acc[mi][nj][3] + bv1;
            if (MODE == 0) {
                *(__half2*)(g_Yh + (size_t)r * C3 + cI) =
                    __floats2half2_rn(v00, v01);
                *(__half2*)(g_Yh + (size_t)(r + 8) * C3 + cI) =
                    __floats2half2_rn(v10, v11);
            } else {
                float2 u0 = {v00, v01}, u1 = {v10, v11};
                *(float2*)(Cext + (size_t)r * DIMC + cI)       = u0;
                *(float2*)(Cext + (size_t)(r + 8) * DIMC + cI) = u1;
            }
        }
    }
}

// =========================================================================
// K-1: pre-convert x to fp16
// =========================================================================
__global__ __launch_bounds__(256)
void convert_x(const float* __restrict__ x)
{
    const size_t i = ((size_t)blockIdx.x * 256 + threadIdx.x) * 8;
    if (i >= (size_t)MROWS * DIMC) return;
    float4 v0 = *(const float4*)(x + i);
    float4 v1 = *(const float4*)(x + i + 4);
    __half2 h[4];
    h[0] = __floats2half2_rn(v0.x, v0.y);
    h[1] = __floats2half2_rn(v0.z, v0.w);
    h[2] = __floats2half2_rn(v1.x, v1.y);
    h[3] = __floats2half2_rn(v1.z, v1.w);
    *(uint4*)(g_Xh + i) = *(uint4*)h;
}

// =========================================================================
// K0: transpose Wqkv [768,2304] -> g_WqkvTh [2304,768], fp16
// =========================================================================
__global__ __launch_bounds__(256)
void transpose_w(const float* __restrict__ W)
{
    __shared__ float tile[32][33];
    const int x = blockIdx.x * 32 + threadIdx.x;
    const int y = blockIdx.y * 32 + threadIdx.y;
#pragma unroll
    for (int i = 0; i < 32; i += 8)
        tile[threadIdx.y + i][threadIdx.x] = W[(size_t)(y + i) * C3 + x];
    __syncthreads();
    const int nx = blockIdx.y * 32 + threadIdx.x;
    const int ny = blockIdx.x * 32 + threadIdx.y;
#pragma unroll
    for (int i = 0; i < 32; i += 8)
        g_WqkvTh[(size_t)(ny + i) * DIMC + nx] =
            __float2half_rn(tile[threadIdx.x][threadIdx.y + i]);
}

// =========================================================================
// K2: Gram partials via fp16 mma (G = Q^T K per (b,h), split-K over seq)
// + per-column sumsq partials. grid (48, 16), 256 threads (8 warps 2m x 4n).
// =========================================================================
__global__ __launch_bounds__(256)
void gram_mma()
{
    const int bh = blockIdx.x;
    const int p  = blockIdx.y;
    const int b  = bh / NHEAD;
    const int h  = bh % NHEAD;

    __shared__ __align__(16) __half Qs[32][72];
    __shared__ __align__(16) __half Ks[32][72];

    const int t    = threadIdx.x;
    const int lane = t & 31;
    const int warp = t >> 5;
    const int wm   = warp >> 2;          // 0..1 -> d offset 0/32
    const int wn   = warp & 3;           // 0..3 -> e offset 0/16/32/48
    const int qrow = lane >> 2;
    const int qcol = lane & 3;

    const int lrow = t >> 3;             // 0..31
    const int lcol = (t & 7) * 8;        // 0..56

    const uint32_t qsb = smem_u32(Qs);
    const uint32_t ksb = smem_u32(Ks);

    float acc[2][2][4] = {};
    float sq = 0.0f;

    const size_t rowbase = (size_t)(b * SEQN + p * RPS);
    const int qoff = h * HD;
    const int koff = DIMC + h * HD;

    // ldmatrix.trans lane addressing (A: k-rows x m-cols; B: k-rows x n-cols)
    const int a_kk = (lane & 7) + ((lane >> 4) & 1) * 8;
    const int a_mm = ((lane >> 3) & 1) * 8;
    const int b_kk = (lane & 7) + ((lane >> 3) & 1) * 8;
    const int b_nn = ((lane >> 4) & 1) * 8;

    for (int kt = 0; kt < RPS / 32; kt++) {
        const size_t gr = (rowbase + kt * 32 + lrow) * C3;
        *(uint4*)&Qs[lrow][lcol] = *(const uint4*)&g_Yh[gr + qoff + lcol];
        *(uint4*)&Ks[lrow][lcol] = *(const uint4*)&g_Yh[gr + koff + lcol];
        __syncthreads();

        if (t < 64) {
#pragma unroll
            for (int r = 0; r < 32; r++) {
                const float v = __half2float(Qs[r][t]);
                sq += v * v;
            }
        } else if (t < 128) {
#pragma unroll
            for (int r = 0; r < 32; r++) {
                const float v = __half2float(Ks[r][t - 64]);
                sq += v * v;
            }
        }

#pragma unroll
        for (int ks = 0; ks < 2; ks++) {
            const int k0 = ks * 16;
            uint32_t a[2][4];
#pragma unroll
            for (int mi = 0; mi < 2; mi++) {
                const int m0 = wm * 32 + mi * 16;
                ldsm4t(a[mi][0], a[mi][1], a[mi][2], a[mi][3],
                       qsb + (uint32_t)((k0 + a_kk) * 72 + m0 + a_mm) * 2);
            }
            uint32_t r0, r1, r2, r3;
            ldsm4t(r0, r1, r2, r3,
                   ksb + (uint32_t)((k0 + b_kk) * 72 + wn * 16 + b_nn) * 2);
            // r0,r1 = (b0,b1) for n-tile 0 ; r2,r3 for n-tile 1
#pragma unroll
            for (int mi = 0; mi < 2; mi++) {
                mma16(acc[mi][0], a[mi], r0, r1);
                mma16(acc[mi][1], a[mi], r2, r3);
            }
        }
        __syncthreads();
    }

    // store G partials
    float* gp = &g_Gp[((size_t)bh * NSPLIT + p) * (HD * HD)];
#pragma unroll
    for (int mi = 0; mi < 2; mi++) {
        const int d = wm * 32 + mi * 16 + qrow;
#pragma unroll
        for (int nj = 0; nj < 2; nj++) {
            const int e = wn * 16 + nj * 8 + qcol * 2;
            gp[d * HD + e]           = acc[mi][nj][0];
            gp[d * HD + e + 1]       = acc[mi][nj][1];
            gp[(d + 8) * HD + e]     = acc[mi][nj][2];
            gp[(d + 8) * HD + e + 1] = acc[mi][nj][3];
        }
    }

    if (t < 64) {
        g_Sqp[((size_t)b * NSPLIT + p) * (2 * DIMC) + h * HD + t] = sq;
    } else if (t < 128) {
        g_Sqp[((size_t)b * NSPLIT + p) * (2 * DIMC) + DIMC + h * HD + (t - 64)] = sq;
    }
}

// =========================================================================
// K3: reduce partials, scale, row softmax -> g_A
// =========================================================================
__global__ __launch_bounds__(256)
void softmax_attn(const float* __restrict__ temperature)
{
    const int bh = blockIdx.x;
    const int b  = bh / NHEAD;
    const int h  = bh % NHEAD;
    const int t  = threadIdx.x;

    __shared__ float Gs[HD][HD + 1];
    __shared__ float rq[HD];
    __shared__ float rk[HD];

    const float* gp = &g_Gp[(size_t)bh * NSPLIT * (HD * HD)];
#pragma unroll
    for (int v = 0; v < 16; v++) {
        const int idx = t * 16 + v;
        float s = 0.0f;
#pragma unroll
        for (int p = 0; p < NSPLIT; p++) s += gp[p * (HD * HD) + idx];
        Gs[idx >> 6][idx & 63] = s;
    }

    if (t < 64) {
        float s = 0.0f;
#pragma unroll
        for (int p = 0; p < NSPLIT; p++)
            s += g_Sqp[((size_t)b * NSPLIT + p) * (2 * DIMC) + h * HD + t];
        rq[t] = temperature[h] / fmaxf(sqrtf(s), 1e-12f);
    } else if (t < 128) {
        const int e = t - 64;
        float s = 0.0f;
#pragma unroll
        for (int p = 0; p < NSPLIT; p++)
            s += g_Sqp[((size_t)b * NSPLIT + p) * (2 * DIMC) + DIMC + h * HD + e];
        rk[e] = 1.0f / fmaxf(sqrtf(s), 1e-12f);
    }
    __syncthreads();

    if (t < 64) {
        const int d = t;
        const float iq = rq[d];
        float mx = -1e30f;
        for (int e = 0; e < HD; e++) {
            const float v = Gs[d][e] * iq * rk[e];
            Gs[d][e] = v;
            mx = fmaxf(mx, v);
        }
        float sum = 0.0f;
        for (int e = 0; e < HD; e++) {
            const float ex = expf(Gs[d][e] - mx);
            Gs[d][e] = ex;
            sum += ex;
        }
        const float inv = 1.0f / sum;
        float* ap = &g_A[(size_t)bh * (HD * HD) + d * HD];
        for (int e = 0; e < HD; e++) ap[e] = Gs[d][e] * inv;
    }
}

// =========================================================================
// K4: WeffTh[b][j][h*64+e] = sum_d A[b,h][d][e] * Wproj[h*64+d][j] (fp16 out)
// =========================================================================
__global__ __launch_bounds__(256)
void weff_kernel(const float* __restrict__ Wproj)
{
    const int jt = blockIdx.x;
    const int bh = blockIdx.y;
    const int b  = bh / NHEAD;
    const int h  = bh % NHEAD;
    const int t  = threadIdx.x;

    __shared__ __align__(16) float A_s[HD][HD];
    __shared__ __align__(16) float W_s[HD][128];

    const float* ap = &g_A[(size_t)bh * (HD * HD)];
#pragma unroll
    for (int v = 0; v < 4; v++) {
        const int idx = t * 16 + v * 4;
        *(float4*)&A_s[idx >> 6][idx & 63] = *(const float4*)&ap[idx];
    }

    const int jbase = jt * 128;
    const int wc  = (t & 31) * 4;
    const int wr0 = t >> 5;
#pragma unroll
    for (int rr = 0; rr < 8; rr++) {
        const int dr = wr0 + rr * 8;
        *(float4*)&W_s[dr][wc] =
            *(const float4*)&Wproj[(size_t)(h * HD + dr) * DIMC + jbase + wc];
    }
    __syncthreads();

    const int e0 = (t >> 5) * 8;
    const int j0 = (t & 31) * 4;
    float acc[8][4] = {};
#pragma unroll
    for (int d = 0; d < HD; d++) {
        float w[4];
        *(float4*)w = *(const float4*)&W_s[d][j0];
#pragma unroll
        for (int i = 0; i < 8; i++) {
            const float a = A_s[d][e0 + i];
#pragma unroll
            for (int j = 0; j < 4; j++) acc[i][j] += a * w[j];
        }
    }

    __half* outT = &g_WeffTh[(size_t)b * DIMC * DIMC + (size_t)jbase * DIMC + h * HD];
#pragma unroll
    for (int i = 0; i < 8; i++)
#pragma unroll
        for (int j = 0; j < 4; j++)
            outT[(size_t)(j0 + j) * DIMC + (e0 + i)] = __float2half_rn(acc[i][j]);
}

// =========================================================================
extern "C" void kernel_launch(void* const* d_in, const int* in_sizes, int n_in,
                              void* d_out, int out_size)
{
    const float* x     = (const float*)d_in[0];
    const float* Wqkv  = (const float*)d_in[1];
    const float* bqkv  = (const float*)d_in[2];
    const float* temp  = (const float*)d_in[3];
    const float* Wproj = (const float*)d_in[4];
    const float* bproj = (const float*)d_in[5];
    float* out = (float*)d_out;

    cudaFuncSetAttribute(gemm_h<0>, cudaFuncAttributeMaxDynamicSharedMemorySize, GSMEM);
    cudaFuncSetAttribute(gemm_h<1>, cudaFuncAttributeMaxDynamicSharedMemorySize, GSMEM);

    // K-1: x -> fp16
    convert_x<<<(MROWS * DIMC / 8 + 255) / 256, 256>>>(x);

    // K0: Wqkv -> transposed fp16
    transpose_w<<<dim3(C3 / 32, DIMC / 32), dim3(32, 8)>>>(Wqkv);

    // K1: Yh = Xh @ WqkvTh + bqkv   [32768 x 2304], fp16 tensor cores
    gemm_h<0><<<dim3(C3 / 128, MROWS / 128), 256, GSMEM>>>(bqkv, nullptr);

    // K2: Gram + sumsq partials (fp16 mma)
    gram_mma<<<dim3(NBH, NSPLIT), 256>>>();

    // K3: reduce + scale + softmax -> A
    softmax_attn<<<NBH, 256>>>(temp);

    // K4: fold A into projection weight per batch (fp16 transposed output)
    weff_kernel<<<dim3(DIMC / 128, NBH), 256>>>(Wproj);

    // K5: Z = Vh @ WeffTh[b] + bproj   [32768 x 768], fp16 tensor cores
    gemm_h<1><<<dim3(DIMC / 128, MROWS / 128), 256, GSMEM>>>(bproj, out);
}